// round 9
// baseline (speedup 1.0000x reference)
#include <cuda_runtime.h>
#include <cuda_bf16.h>
#include <cstdint>
#include <cstddef>

#define NN     50000
#define NE     800000
#define INC    128
#define HID    64
#define HEADS  4
#define D1     256          // HEADS*HID
#define OUTC   10
#define NG     500
#define NEG    0.2f

// ---------------- scratch (device globals; allocation-free) ----------------
__device__ __align__(16) float g_h1  [NN * D1];      // x @ W1
__device__ __align__(16) float g_out1[NN * D1];      // relu(GAT1 + b1)
__device__ __align__(16) float g_als1[NN * HEADS];
__device__ __align__(16) float g_ald1[NN * HEADS];
__device__ __align__(16) float g_h2  [NN * HID];     // out1 @ W2
__device__ float g_als2[NN], g_ald2[NN];
__device__ __align__(16) float g_pool[NG * HID];

// index handling + CSR (dst-sorted)
__device__ int g_is64;
__device__ int g_src[NE];
__device__ int g_dst[NE];
__device__ int g_bat[NN];
__device__ int g_deg[NN];
__device__ int g_row[NN + 1];
__device__ int g_cur[NN];
__device__ int g_csr_src[NE];

// ---------------- helpers ----------------
__device__ __forceinline__ float leaky(float v) { return v > 0.f ? v : NEG * v; }

__device__ __forceinline__ void red4(float* p, float4 v) {
    asm volatile("red.global.add.v4.f32 [%0], {%1,%2,%3,%4};"
                 :: "l"(p), "f"(v.x), "f"(v.y), "f"(v.z), "f"(v.w) : "memory");
}

// ---------------- prep: detect index dtype + zero degree array ----------
__global__ void prep_k(const int* __restrict__ raw) {
    int n = blockIdx.x * blockDim.x + threadIdx.x;
    if (n < NN) g_deg[n] = 0;
    if (n == 0) {
        int acc = 0;
#pragma unroll 1
        for (int i = 1; i < 128; i += 2) acc |= raw[i];
        g_is64 = (acc == 0) ? 1 : 0;   // int64 LE: high words all zero
    }
}

// convert edges (+ batch for first NN threads) and build degree histogram
__global__ void cvt_k(const int* __restrict__ eraw, const int* __restrict__ braw) {
    int e = blockIdx.x * blockDim.x + threadIdx.x;
    if (e >= NE) return;
    int s, d;
    if (g_is64) {
        const long long* p = (const long long*)eraw;
        s = (int)p[e];
        d = (int)p[(size_t)NE + e];
        if (e < NN) g_bat[e] = (int)((const long long*)braw)[e];
    } else {
        s = eraw[e];
        d = eraw[NE + e];
        if (e < NN) g_bat[e] = braw[e];
    }
    g_src[e] = s;
    g_dst[e] = d;
    atomicAdd(&g_deg[d], 1);
}

// single-block exclusive scan over g_deg -> g_row; inits g_cur
__global__ __launch_bounds__(1024) void scan_k() {
    __shared__ int wsum[32];
    __shared__ int s_carry;
    const int tid = threadIdx.x, lane = tid & 31, wid = tid >> 5;
    if (tid == 0) s_carry = 0;
    __syncthreads();
    for (int base = 0; base < NN; base += 1024) {
        int i = base + tid;
        int v = (i < NN) ? g_deg[i] : 0;
        int incl = v;
#pragma unroll
        for (int off = 1; off < 32; off <<= 1) {
            int t = __shfl_up_sync(0xFFFFFFFFu, incl, off);
            if (lane >= off) incl += t;
        }
        if (lane == 31) wsum[wid] = incl;
        __syncthreads();
        if (wid == 0) {
            int w = wsum[lane];
            int wi = w;
#pragma unroll
            for (int off = 1; off < 32; off <<= 1) {
                int t = __shfl_up_sync(0xFFFFFFFFu, wi, off);
                if (lane >= off) wi += t;
            }
            wsum[lane] = wi - w;
        }
        __syncthreads();
        int c = s_carry;
        int excl = c + wsum[wid] + incl - v;
        if (i < NN) {
            g_row[i] = excl;
            g_cur[i] = excl;
        }
        __syncthreads();
        if (tid == 1023) s_carry = c + wsum[31] + incl;
        __syncthreads();
    }
    if (tid == 0) g_row[NN] = s_carry;
}

__global__ void place_k() {
    int e = blockIdx.x * blockDim.x + threadIdx.x;
    if (e >= NE) return;
    int p = atomicAdd(&g_cur[g_dst[e]], 1);
    g_csr_src[p] = g_src[e];
}

// ---------------- SGEMM: C[M,N] = A[M,K] @ B[K,N] ----------------
// BM=128, BK=8, BN=16*TN; 256 threads; TMxTN = 8xTN microtile; double-buffered.
template<int BN, int TN>
__global__ __launch_bounds__(256) void sgemm_t(const float* __restrict__ A,
                                               const float* __restrict__ B,
                                               float* __restrict__ C,
                                               int M, int N, int K) {
    constexpr int BM = 128, BK = 8;
    static_assert(BN == 16 * TN, "layout");
    __shared__ __align__(16) float As[2][BK][BM];
    __shared__ __align__(16) float Bs[2][BK][BN];

    const int tid = threadIdx.x;
    const int tx = tid & 15, ty = tid >> 4;
    const int m0 = blockIdx.y * BM, n0 = blockIdx.x * BN;

    const int arow = tid >> 1, akc = (tid & 1) * 4;
    const bool aok = (m0 + arow) < M;
    int brow, bcol;
    bool bldr;
    if (BN == 128) { brow = tid >> 5; bcol = (tid & 31) * 4; bldr = true; }
    else           { brow = tid >> 4; bcol = (tid & 15) * 4; bldr = (tid < 128); }

    float acc[8][TN];
#pragma unroll
    for (int i = 0; i < 8; i++)
#pragma unroll
        for (int j = 0; j < TN; j++) acc[i][j] = 0.f;

    const int T = K / BK;

    // preload tile 0
    {
        float4 fa = make_float4(0.f, 0.f, 0.f, 0.f);
        if (aok) fa = *(const float4*)(A + (size_t)(m0 + arow) * K + akc);
        As[0][akc + 0][arow] = fa.x; As[0][akc + 1][arow] = fa.y;
        As[0][akc + 2][arow] = fa.z; As[0][akc + 3][arow] = fa.w;
        if (bldr)
            *(float4*)&Bs[0][brow][bcol] = *(const float4*)(B + (size_t)brow * N + n0 + bcol);
    }
    __syncthreads();

    for (int t = 0; t < T; t++) {
        const int cur = t & 1;
        float4 na = make_float4(0.f, 0.f, 0.f, 0.f), nb;
        const bool has = (t + 1 < T);
        if (has) {
            if (aok) na = *(const float4*)(A + (size_t)(m0 + arow) * K + (t + 1) * BK + akc);
            if (bldr) nb = *(const float4*)(B + (size_t)((t + 1) * BK + brow) * N + n0 + bcol);
        }
#pragma unroll
        for (int k = 0; k < BK; k++) {
            float a[8], b[TN];
            *(float4*)&a[0] = *(const float4*)&As[cur][k][ty * 8];
            *(float4*)&a[4] = *(const float4*)&As[cur][k][ty * 8 + 4];
            *(float4*)&b[0] = *(const float4*)&Bs[cur][k][tx * TN];
            if (TN == 8) *(float4*)&b[4] = *(const float4*)&Bs[cur][k][tx * TN + 4];
#pragma unroll
            for (int i = 0; i < 8; i++)
#pragma unroll
                for (int j = 0; j < TN; j++) acc[i][j] = fmaf(a[i], b[j], acc[i][j]);
        }
        if (has) {
            const int nxt = cur ^ 1;
            As[nxt][akc + 0][arow] = na.x; As[nxt][akc + 1][arow] = na.y;
            As[nxt][akc + 2][arow] = na.z; As[nxt][akc + 3][arow] = na.w;
            if (bldr) *(float4*)&Bs[nxt][brow][bcol] = nb;
            __syncthreads();
        }
    }

#pragma unroll
    for (int i = 0; i < 8; i++) {
        int gr = m0 + ty * 8 + i;
        if (gr < M) {
            float* cp = C + (size_t)gr * N + n0 + tx * TN;
            *(float4*)cp = make_float4(acc[i][0], acc[i][1], acc[i][2], acc[i][3]);
            if (TN == 8)
                *(float4*)(cp + 4) = make_float4(acc[i][4], acc[i][5], acc[i][6], acc[i][7]);
        }
    }
}

// ---------------- attention coefficients ----------------
__global__ void al1_k(const float* __restrict__ a_src, const float* __restrict__ a_dst) {
    int t = blockIdx.x * blockDim.x + threadIdx.x;
    if (t >= NN * HEADS) return;
    int n = t >> 2, h = t & 3;
    const float4* hr = (const float4*)(g_h1 + (size_t)n * D1 + h * HID);
    const float4* as = (const float4*)(a_src + h * HID);
    const float4* ad = (const float4*)(a_dst + h * HID);
    float ss = 0.f, sd = 0.f;
#pragma unroll
    for (int j = 0; j < 16; j++) {
        float4 v = hr[j], a = as[j], b = ad[j];
        ss += v.x * a.x + v.y * a.y + v.z * a.z + v.w * a.w;
        sd += v.x * b.x + v.y * b.y + v.z * b.z + v.w * b.w;
    }
    g_als1[t] = ss;
    g_ald1[t] = sd;
}

// also zeroes the pooled output (independent work, saves a launch)
__global__ void al2_k(const float* __restrict__ a_src, const float* __restrict__ a_dst) {
    int n = blockIdx.x * blockDim.x + threadIdx.x;
    if (n < NG * HID) g_pool[n] = 0.f;
    if (n >= NN) return;
    const float4* hr = (const float4*)(g_h2 + (size_t)n * HID);
    const float4* as = (const float4*)a_src;
    const float4* ad = (const float4*)a_dst;
    float ss = 0.f, sd = 0.f;
#pragma unroll
    for (int j = 0; j < 16; j++) {
        float4 v = hr[j], a = as[j], b = ad[j];
        ss += v.x * a.x + v.y * a.y + v.z * a.z + v.w * a.w;
        sd += v.x * b.x + v.y * b.y + v.z * b.z + v.w * b.w;
    }
    g_als2[n] = ss;
    g_ald2[n] = sd;
}

// ------- layer 1: fused single-pass softmax + aggregate + bias + relu -------
// exp(e)/sum exp(e) == exp(e-m)/sum exp(e-m); logits are O(10), overflow-safe.
// warp per dst node; lane owns channels [lane*8, lane*8+8), head h = lane>>3
__global__ __launch_bounds__(256) void agg1_k(const float* __restrict__ b1) {
    int node = (blockIdx.x * blockDim.x + threadIdx.x) >> 5;
    int lane = threadIdx.x & 31;
    if (node >= NN) return;
    const int h = lane >> 3;
    const int beg = g_row[node], end = g_row[node + 1];

    const float ald = g_ald1[node * 4 + h];
    float ex = __expf(leaky(g_als1[node * 4 + h] + ald));  // self-loop term
    float den = ex;
    float acc[8];
    {
        const float4* hp = (const float4*)(g_h1 + (size_t)node * D1 + lane * 8);
        float4 v0 = hp[0], v1 = hp[1];
        acc[0] = ex * v0.x; acc[1] = ex * v0.y; acc[2] = ex * v0.z; acc[3] = ex * v0.w;
        acc[4] = ex * v1.x; acc[5] = ex * v1.y; acc[6] = ex * v1.z; acc[7] = ex * v1.w;
    }
    int s_next = (beg < end) ? g_csr_src[beg] : 0;
    for (int i = beg; i < end; i++) {
        int s = s_next;
        if (i + 1 < end) s_next = g_csr_src[i + 1];
        float w = __expf(leaky(g_als1[s * 4 + h] + ald));
        den += w;
        const float4* hp = (const float4*)(g_h1 + (size_t)s * D1 + lane * 8);
        float4 v0 = hp[0], v1 = hp[1];
        acc[0] = fmaf(w, v0.x, acc[0]); acc[1] = fmaf(w, v0.y, acc[1]);
        acc[2] = fmaf(w, v0.z, acc[2]); acc[3] = fmaf(w, v0.w, acc[3]);
        acc[4] = fmaf(w, v1.x, acc[4]); acc[5] = fmaf(w, v1.y, acc[5]);
        acc[6] = fmaf(w, v1.z, acc[6]); acc[7] = fmaf(w, v1.w, acc[7]);
    }
    float inv = 1.f / (den + 1e-16f);
    const float4* bp = (const float4*)(b1 + lane * 8);
    float4 b0 = bp[0], b4 = bp[1];
    float4 o0 = make_float4(fmaxf(fmaf(acc[0], inv, b0.x), 0.f),
                            fmaxf(fmaf(acc[1], inv, b0.y), 0.f),
                            fmaxf(fmaf(acc[2], inv, b0.z), 0.f),
                            fmaxf(fmaf(acc[3], inv, b0.w), 0.f));
    float4 o1 = make_float4(fmaxf(fmaf(acc[4], inv, b4.x), 0.f),
                            fmaxf(fmaf(acc[5], inv, b4.y), 0.f),
                            fmaxf(fmaf(acc[6], inv, b4.z), 0.f),
                            fmaxf(fmaf(acc[7], inv, b4.w), 0.f));
    float4* op = (float4*)(g_out1 + (size_t)node * D1 + lane * 8);
    op[0] = o0; op[1] = o1;
}

// ------- layer 2: fused single-pass softmax + aggregate + bias + pool -------
// warp per dst node; lane owns channels [lane*2, lane*2+2); H=1
__global__ __launch_bounds__(256) void agg2_k(const float* __restrict__ b2) {
    int node = (blockIdx.x * blockDim.x + threadIdx.x) >> 5;
    int lane = threadIdx.x & 31;
    if (node >= NN) return;
    const int beg = g_row[node], end = g_row[node + 1];

    const float ald = g_ald2[node];
    float ex = __expf(leaky(g_als2[node] + ald));
    float den = ex;
    float a0, a1;
    {
        float2 v = *(const float2*)(g_h2 + (size_t)node * HID + lane * 2);
        a0 = ex * v.x; a1 = ex * v.y;
    }
    int s_next = (beg < end) ? g_csr_src[beg] : 0;
    for (int i = beg; i < end; i++) {
        int s = s_next;
        if (i + 1 < end) s_next = g_csr_src[i + 1];
        float w = __expf(leaky(g_als2[s] + ald));
        den += w;
        float2 v = *(const float2*)(g_h2 + (size_t)s * HID + lane * 2);
        a0 = fmaf(w, v.x, a0);
        a1 = fmaf(w, v.y, a1);
    }
    float inv = 1.f / (den + 1e-16f);
    float2 bb = *(const float2*)(b2 + lane * 2);
    float v0 = fmaf(a0, inv, bb.x);
    float v1 = fmaf(a1, inv, bb.y);

    float u0 = __shfl_down_sync(0xFFFFFFFFu, v0, 1);
    float u1 = __shfl_down_sync(0xFFFFFFFFu, v1, 1);
    if ((lane & 1) == 0) {
        int g = g_bat[node];
        red4(&g_pool[g * HID + lane * 2], make_float4(v0, v1, u0, u1));
    }
}

// ---------------- classifier ----------------
__global__ void cls_k(const float* __restrict__ fcw, const float* __restrict__ fcb,
                      float* __restrict__ out) {
    int g = blockIdx.x * blockDim.x + threadIdx.x;
    if (g >= NG) return;
    float l[OUTC];
#pragma unroll
    for (int j = 0; j < OUTC; j++) l[j] = fcb[j];
    for (int k = 0; k < HID; k++) {
        float p = g_pool[g * HID + k];
#pragma unroll
        for (int j = 0; j < OUTC; j++) l[j] = fmaf(p, fcw[k * OUTC + j], l[j]);
    }
    float mx = l[0];
#pragma unroll
    for (int j = 1; j < OUTC; j++) mx = fmaxf(mx, l[j]);
    float s = 0.f;
#pragma unroll
    for (int j = 0; j < OUTC; j++) s += expf(l[j] - mx);
    float lse = mx + logf(s);
#pragma unroll
    for (int j = 0; j < OUTC; j++) out[g * OUTC + j] = l[j] - lse;
}

// ---------------- launch ----------------
extern "C" void kernel_launch(void* const* d_in, const int* in_sizes, int n_in,
                              void* d_out, int out_size) {
    const float* x      = (const float*)d_in[0];
    const int*   ei_raw = (const int*)d_in[1];
    const int*   b_raw  = (const int*)d_in[2];
    const float* W1     = (const float*)d_in[3];
    const float* a_src1 = (const float*)d_in[4];
    const float* a_dst1 = (const float*)d_in[5];
    const float* b1     = (const float*)d_in[6];
    const float* W2     = (const float*)d_in[7];
    const float* a_src2 = (const float*)d_in[8];
    const float* a_dst2 = (const float*)d_in[9];
    const float* b2     = (const float*)d_in[10];
    const float* fcw    = (const float*)d_in[11];
    const float* fcb    = (const float*)d_in[12];
    float*       out    = (float*)d_out;

    void *p_h1, *p_out1, *p_h2;
    cudaGetSymbolAddress(&p_h1, g_h1);
    cudaGetSymbolAddress(&p_out1, g_out1);
    cudaGetSymbolAddress(&p_h2, g_h2);

    const int T = 256;
    const int gN4 = (NN * HEADS + T - 1) / T;
    const int gN  = (NN + T - 1) / T;
    const int gE  = (NE + T - 1) / T;
    const int gNw = (NN * 32 + T - 1) / T;   // warp per node

    // ---- index conversion + CSR build ----
    prep_k<<<gN, T>>>(ei_raw);
    cvt_k<<<gE, T>>>(ei_raw, b_raw);
    scan_k<<<1, 1024>>>();
    place_k<<<gE, T>>>();

    // ---- GAT layer 1 ----
    sgemm_t<128, 8><<<dim3(D1 / 128, (NN + 127) / 128), 256>>>(x, W1, (float*)p_h1,
                                                               NN, D1, INC);
    al1_k<<<gN4, T>>>(a_src1, a_dst1);
    agg1_k<<<gNw, T>>>(b1);

    // ---- GAT layer 2 (+ fused pooling) ----
    sgemm_t<64, 4><<<dim3(1, (NN + 127) / 128), 256>>>((const float*)p_out1, W2,
                                                       (float*)p_h2, NN, HID, D1);
    al2_k<<<gN, T>>>(a_src2, a_dst2);
    agg2_k<<<gNw, T>>>(b2);

    // ---- classifier ----
    cls_k<<<(NG + T - 1) / T, T>>>(fcw, fcb, out);
}

// round 10
// speedup vs baseline: 1.1826x; 1.1826x over previous
#include <cuda_runtime.h>
#include <cuda_bf16.h>
#include <cstdint>
#include <cstddef>

#define NN     50000
#define NE     800000
#define INC    128
#define HID    64
#define HEADS  4
#define D1     256          // HEADS*HID
#define OUTC   10
#define NG     500
#define NEG    0.2f

// ---------------- scratch (device globals; allocation-free) ----------------
__device__ __align__(16) __nv_bfloat16 g_h1b[NN * D1];   // x @ W1   (bf16)
__device__ __align__(16) float         g_out1[NN * D1];  // relu(GAT1 + b1) fp32
__device__ __align__(16) __nv_bfloat16 g_h2b[NN * HID];  // out1 @ W2 (bf16)
__device__ __align__(16) float g_als1[NN * HEADS];
__device__ __align__(16) float g_ald1[NN * HEADS];
__device__ float g_als2[NN], g_ald2[NN];
__device__ __align__(16) float g_pool[NG * HID];

// index handling + CSR (dst-sorted)
__device__ int g_is64;
__device__ int g_src[NE];
__device__ int g_dst[NE];
__device__ int g_bat[NN];
__device__ int g_deg[NN];
__device__ int g_row[NN + 1];
__device__ int g_cur[NN];
__device__ int g_csr_src[NE];

// ---------------- helpers ----------------
__device__ __forceinline__ float leaky(float v) { return v > 0.f ? v : NEG * v; }

__device__ __forceinline__ void red4(float* p, float4 v) {
    asm volatile("red.global.add.v4.f32 [%0], {%1,%2,%3,%4};"
                 :: "l"(p), "f"(v.x), "f"(v.y), "f"(v.z), "f"(v.w) : "memory");
}

// unpack 8 bf16 (one uint4) into 8 floats
__device__ __forceinline__ void unp8(uint4 u, float* f) {
    float2 p;
    p = __bfloat1622float2(*(const __nv_bfloat162*)&u.x); f[0] = p.x; f[1] = p.y;
    p = __bfloat1622float2(*(const __nv_bfloat162*)&u.y); f[2] = p.x; f[3] = p.y;
    p = __bfloat1622float2(*(const __nv_bfloat162*)&u.z); f[4] = p.x; f[5] = p.y;
    p = __bfloat1622float2(*(const __nv_bfloat162*)&u.w); f[6] = p.x; f[7] = p.y;
}

// ---------------- prep: detect index dtype + zero degree array ----------
__global__ void prep_k(const int* __restrict__ raw) {
    int n = blockIdx.x * blockDim.x + threadIdx.x;
    if (n < NN) g_deg[n] = 0;
    if (n == 0) {
        int acc = 0;
#pragma unroll 1
        for (int i = 1; i < 128; i += 2) acc |= raw[i];
        g_is64 = (acc == 0) ? 1 : 0;   // int64 LE: high words all zero
    }
}

__global__ void cvt_k(const int* __restrict__ eraw, const int* __restrict__ braw) {
    int e = blockIdx.x * blockDim.x + threadIdx.x;
    if (e >= NE) return;
    int s, d;
    if (g_is64) {
        const long long* p = (const long long*)eraw;
        s = (int)p[e];
        d = (int)p[(size_t)NE + e];
        if (e < NN) g_bat[e] = (int)((const long long*)braw)[e];
    } else {
        s = eraw[e];
        d = eraw[NE + e];
        if (e < NN) g_bat[e] = braw[e];
    }
    g_src[e] = s;
    g_dst[e] = d;
    atomicAdd(&g_deg[d], 1);
}

// single-block exclusive scan over g_deg -> g_row; inits g_cur
__global__ __launch_bounds__(1024) void scan_k() {
    __shared__ int wsum[32];
    __shared__ int s_carry;
    const int tid = threadIdx.x, lane = tid & 31, wid = tid >> 5;
    if (tid == 0) s_carry = 0;
    __syncthreads();
    for (int base = 0; base < NN; base += 1024) {
        int i = base + tid;
        int v = (i < NN) ? g_deg[i] : 0;
        int incl = v;
#pragma unroll
        for (int off = 1; off < 32; off <<= 1) {
            int t = __shfl_up_sync(0xFFFFFFFFu, incl, off);
            if (lane >= off) incl += t;
        }
        if (lane == 31) wsum[wid] = incl;
        __syncthreads();
        if (wid == 0) {
            int w = wsum[lane];
            int wi = w;
#pragma unroll
            for (int off = 1; off < 32; off <<= 1) {
                int t = __shfl_up_sync(0xFFFFFFFFu, wi, off);
                if (lane >= off) wi += t;
            }
            wsum[lane] = wi - w;
        }
        __syncthreads();
        int c = s_carry;
        int excl = c + wsum[wid] + incl - v;
        if (i < NN) {
            g_row[i] = excl;
            g_cur[i] = excl;
        }
        __syncthreads();
        if (tid == 1023) s_carry = c + wsum[31] + incl;
        __syncthreads();
    }
    if (tid == 0) g_row[NN] = s_carry;
}

__global__ void place_k() {
    int e = blockIdx.x * blockDim.x + threadIdx.x;
    if (e >= NE) return;
    int p = atomicAdd(&g_cur[g_dst[e]], 1);
    g_csr_src[p] = g_src[e];
}

// -------- SGEMM (R6-proven config): C_bf16[M,N] = A[M,K] @ B[K,N] ----------
// BM=128, BN=64, BK=16; 256 threads; 8x4 microtile.
__global__ __launch_bounds__(256) void sgemm_k(const float* __restrict__ A,
                                               const float* __restrict__ B,
                                               __nv_bfloat16* __restrict__ C,
                                               int M, int N, int K) {
    __shared__ __align__(16) float As[16][128];
    __shared__ __align__(16) float Bs[16][64];
    const int tid = threadIdx.x;
    const int tx = tid & 15, ty = tid >> 4;
    const int m0 = blockIdx.y * 128, n0 = blockIdx.x * 64;

    float acc[8][4];
#pragma unroll
    for (int i = 0; i < 8; i++)
#pragma unroll
        for (int j = 0; j < 4; j++) acc[i][j] = 0.f;

    for (int k0 = 0; k0 < K; k0 += 16) {
#pragma unroll
        for (int v = 0; v < 2; v++) {
            int id  = tid + v * 256;
            int row = id >> 2;
            int kc  = (id & 3) << 2;
            float4 f = make_float4(0.f, 0.f, 0.f, 0.f);
            int gr = m0 + row;
            if (gr < M) f = *(const float4*)(A + (size_t)gr * K + k0 + kc);
            As[kc + 0][row] = f.x; As[kc + 1][row] = f.y;
            As[kc + 2][row] = f.z; As[kc + 3][row] = f.w;
        }
        {
            int kk = tid >> 4;
            int nc = (tid & 15) << 2;
            *(float4*)&Bs[kk][nc] = *(const float4*)(B + (size_t)(k0 + kk) * N + n0 + nc);
        }
        __syncthreads();
#pragma unroll
        for (int kk = 0; kk < 16; kk++) {
            float a[8], b[4];
            *(float4*)&a[0] = *(const float4*)&As[kk][ty * 8];
            *(float4*)&a[4] = *(const float4*)&As[kk][ty * 8 + 4];
            *(float4*)&b[0] = *(const float4*)&Bs[kk][tx * 4];
#pragma unroll
            for (int i = 0; i < 8; i++)
#pragma unroll
                for (int j = 0; j < 4; j++) acc[i][j] = fmaf(a[i], b[j], acc[i][j]);
        }
        __syncthreads();
    }
#pragma unroll
    for (int i = 0; i < 8; i++) {
        int gr = m0 + ty * 8 + i;
        if (gr < M) {
            __nv_bfloat162* cp = (__nv_bfloat162*)(C + (size_t)gr * N + n0 + tx * 4);
            cp[0] = __floats2bfloat162_rn(acc[i][0], acc[i][1]);
            cp[1] = __floats2bfloat162_rn(acc[i][2], acc[i][3]);
        }
    }
}

// ---------------- attention coefficients (bf16 features) ----------------
__global__ void al1_k(const float* __restrict__ a_src, const float* __restrict__ a_dst) {
    int t = blockIdx.x * blockDim.x + threadIdx.x;
    if (t >= NN * HEADS) return;
    int n = t >> 2, h = t & 3;
    const uint4* hr = (const uint4*)(g_h1b + (size_t)n * D1 + h * HID);  // 8 x uint4
    const float4* as = (const float4*)(a_src + h * HID);
    const float4* ad = (const float4*)(a_dst + h * HID);
    float ss = 0.f, sd = 0.f;
#pragma unroll
    for (int j = 0; j < 8; j++) {
        float f[8];
        unp8(hr[j], f);
        float4 a0 = as[2 * j], a1 = as[2 * j + 1];
        float4 b0 = ad[2 * j], b1 = ad[2 * j + 1];
        ss += f[0] * a0.x + f[1] * a0.y + f[2] * a0.z + f[3] * a0.w
            + f[4] * a1.x + f[5] * a1.y + f[6] * a1.z + f[7] * a1.w;
        sd += f[0] * b0.x + f[1] * b0.y + f[2] * b0.z + f[3] * b0.w
            + f[4] * b1.x + f[5] * b1.y + f[6] * b1.z + f[7] * b1.w;
    }
    g_als1[t] = ss;
    g_ald1[t] = sd;
}

// also zeroes the pooled output (independent work, saves a launch)
__global__ void al2_k(const float* __restrict__ a_src, const float* __restrict__ a_dst) {
    int n = blockIdx.x * blockDim.x + threadIdx.x;
    if (n < NG * HID) g_pool[n] = 0.f;
    if (n >= NN) return;
    const uint4* hr = (const uint4*)(g_h2b + (size_t)n * HID);
    const float4* as = (const float4*)a_src;
    const float4* ad = (const float4*)a_dst;
    float ss = 0.f, sd = 0.f;
#pragma unroll
    for (int j = 0; j < 8; j++) {
        float f[8];
        unp8(hr[j], f);
        float4 a0 = as[2 * j], a1 = as[2 * j + 1];
        float4 b0 = ad[2 * j], b1 = ad[2 * j + 1];
        ss += f[0] * a0.x + f[1] * a0.y + f[2] * a0.z + f[3] * a0.w
            + f[4] * a1.x + f[5] * a1.y + f[6] * a1.z + f[7] * a1.w;
        sd += f[0] * b0.x + f[1] * b0.y + f[2] * b0.z + f[3] * b0.w
            + f[4] * b1.x + f[5] * b1.y + f[6] * b1.z + f[7] * b1.w;
    }
    g_als2[n] = ss;
    g_ald2[n] = sd;
}

// ------- layer 1: fused single-pass softmax + aggregate + bias + relu -------
// warp per dst node; lane owns channels [lane*8, lane*8+8), head h = lane>>3;
// one uint4 (8 bf16) gather per lane per edge.
__global__ __launch_bounds__(256) void agg1_k(const float* __restrict__ b1) {
    int node = (blockIdx.x * blockDim.x + threadIdx.x) >> 5;
    int lane = threadIdx.x & 31;
    if (node >= NN) return;
    const int h = lane >> 3;
    const int beg = g_row[node], end = g_row[node + 1];

    const float ald = g_ald1[node * 4 + h];
    float ex = __expf(leaky(g_als1[node * 4 + h] + ald));  // self-loop term
    float den = ex;
    float acc[8];
    {
        float f[8];
        unp8(*(const uint4*)(g_h1b + (size_t)node * D1 + lane * 8), f);
#pragma unroll
        for (int c = 0; c < 8; c++) acc[c] = ex * f[c];
    }
    for (int i = beg; i < end; i++) {
        int s = g_csr_src[i];
        float w = __expf(leaky(g_als1[s * 4 + h] + ald));
        den += w;
        float f[8];
        unp8(*(const uint4*)(g_h1b + (size_t)s * D1 + lane * 8), f);
#pragma unroll
        for (int c = 0; c < 8; c++) acc[c] = fmaf(w, f[c], acc[c]);
    }
    float inv = 1.f / (den + 1e-16f);
    const float4* bp = (const float4*)(b1 + lane * 8);
    float4 b0 = bp[0], b4 = bp[1];
    float4 o0 = make_float4(fmaxf(fmaf(acc[0], inv, b0.x), 0.f),
                            fmaxf(fmaf(acc[1], inv, b0.y), 0.f),
                            fmaxf(fmaf(acc[2], inv, b0.z), 0.f),
                            fmaxf(fmaf(acc[3], inv, b0.w), 0.f));
    float4 o1 = make_float4(fmaxf(fmaf(acc[4], inv, b4.x), 0.f),
                            fmaxf(fmaf(acc[5], inv, b4.y), 0.f),
                            fmaxf(fmaf(acc[6], inv, b4.z), 0.f),
                            fmaxf(fmaf(acc[7], inv, b4.w), 0.f));
    float4* op = (float4*)(g_out1 + (size_t)node * D1 + lane * 8);
    op[0] = o0; op[1] = o1;
}

// ------- layer 2: fused single-pass softmax + aggregate + bias + pool -------
// warp per dst node; lane owns channels [lane*2, lane*2+2); H=1; bf16 gather.
__global__ __launch_bounds__(256) void agg2_k(const float* __restrict__ b2) {
    int node = (blockIdx.x * blockDim.x + threadIdx.x) >> 5;
    int lane = threadIdx.x & 31;
    if (node >= NN) return;
    const int beg = g_row[node], end = g_row[node + 1];

    const float ald = g_ald2[node];
    float ex = __expf(leaky(g_als2[node] + ald));
    float den = ex;
    float a0, a1;
    {
        float2 v = __bfloat1622float2(
            *(const __nv_bfloat162*)(g_h2b + (size_t)node * HID + lane * 2));
        a0 = ex * v.x; a1 = ex * v.y;
    }
    for (int i = beg; i < end; i++) {
        int s = g_csr_src[i];
        float w = __expf(leaky(g_als2[s] + ald));
        den += w;
        float2 v = __bfloat1622float2(
            *(const __nv_bfloat162*)(g_h2b + (size_t)s * HID + lane * 2));
        a0 = fmaf(w, v.x, a0);
        a1 = fmaf(w, v.y, a1);
    }
    float inv = 1.f / (den + 1e-16f);
    float2 bb = *(const float2*)(b2 + lane * 2);
    float v0 = fmaf(a0, inv, bb.x);
    float v1 = fmaf(a1, inv, bb.y);

    float u0 = __shfl_down_sync(0xFFFFFFFFu, v0, 1);
    float u1 = __shfl_down_sync(0xFFFFFFFFu, v1, 1);
    if ((lane & 1) == 0) {
        int g = g_bat[node];
        red4(&g_pool[g * HID + lane * 2], make_float4(v0, v1, u0, u1));
    }
}

// ---------------- classifier ----------------
__global__ void cls_k(const float* __restrict__ fcw, const float* __restrict__ fcb,
                      float* __restrict__ out) {
    int g = blockIdx.x * blockDim.x + threadIdx.x;
    if (g >= NG) return;
    float l[OUTC];
#pragma unroll
    for (int j = 0; j < OUTC; j++) l[j] = fcb[j];
    for (int k = 0; k < HID; k++) {
        float p = g_pool[g * HID + k];
#pragma unroll
        for (int j = 0; j < OUTC; j++) l[j] = fmaf(p, fcw[k * OUTC + j], l[j]);
    }
    float mx = l[0];
#pragma unroll
    for (int j = 1; j < OUTC; j++) mx = fmaxf(mx, l[j]);
    float s = 0.f;
#pragma unroll
    for (int j = 0; j < OUTC; j++) s += expf(l[j] - mx);
    float lse = mx + logf(s);
#pragma unroll
    for (int j = 0; j < OUTC; j++) out[g * OUTC + j] = l[j] - lse;
}

// ---------------- launch ----------------
extern "C" void kernel_launch(void* const* d_in, const int* in_sizes, int n_in,
                              void* d_out, int out_size) {
    const float* x      = (const float*)d_in[0];
    const int*   ei_raw = (const int*)d_in[1];
    const int*   b_raw  = (const int*)d_in[2];
    const float* W1     = (const float*)d_in[3];
    const float* a_src1 = (const float*)d_in[4];
    const float* a_dst1 = (const float*)d_in[5];
    const float* b1     = (const float*)d_in[6];
    const float* W2     = (const float*)d_in[7];
    const float* a_src2 = (const float*)d_in[8];
    const float* a_dst2 = (const float*)d_in[9];
    const float* b2     = (const float*)d_in[10];
    const float* fcw    = (const float*)d_in[11];
    const float* fcb    = (const float*)d_in[12];
    float*       out    = (float*)d_out;

    void *p_h1b, *p_out1, *p_h2b;
    cudaGetSymbolAddress(&p_h1b, g_h1b);
    cudaGetSymbolAddress(&p_out1, g_out1);
    cudaGetSymbolAddress(&p_h2b, g_h2b);

    const int T = 256;
    const int gN4 = (NN * HEADS + T - 1) / T;
    const int gN  = (NN + T - 1) / T;
    const int gE  = (NE + T - 1) / T;
    const int gNw = (NN * 32 + T - 1) / T;   // warp per node

    // ---- index conversion + CSR build ----
    prep_k<<<gN, T>>>(ei_raw);
    cvt_k<<<gE, T>>>(ei_raw, b_raw);
    scan_k<<<1, 1024>>>();
    place_k<<<gE, T>>>();

    // ---- GAT layer 1 ----
    sgemm_k<<<dim3(D1 / 64, (NN + 127) / 128), 256>>>(x, W1, (__nv_bfloat16*)p_h1b,
                                                      NN, D1, INC);
    al1_k<<<gN4, T>>>(a_src1, a_dst1);
    agg1_k<<<gNw, T>>>(b1);

    // ---- GAT layer 2 (+ fused pooling) ----
    sgemm_k<<<dim3(HID / 64, (NN + 127) / 128), 256>>>((const float*)p_out1, W2,
                                                       (__nv_bfloat16*)p_h2b,
                                                       NN, HID, D1);
    al2_k<<<gN, T>>>(a_src2, a_dst2);
    agg2_k<<<gNw, T>>>(b2);

    // ---- classifier ----
    cls_k<<<(NG + T - 1) / T, T>>>(fcw, fcb, out);
}

// round 11
// speedup vs baseline: 1.4699x; 1.2429x over previous
#include <cuda_runtime.h>
#include <cuda_bf16.h>
#include <cstdint>
#include <cstddef>

#define NN     50000
#define NE     800000
#define INC    128
#define HID    64
#define HEADS  4
#define D1     256          // HEADS*HID
#define OUTC   10
#define NG     500
#define NEG    0.2f

// ---------------- scratch (device globals; allocation-free) ----------------
__device__ __align__(16) __nv_bfloat16 g_h1b[NN * D1];   // x @ W1   (bf16)
__device__ __align__(16) float         g_out1[NN * D1];  // relu(GAT1 + b1) fp32
__device__ __align__(16) __nv_bfloat16 g_h2b[NN * HID];  // out1 @ W2 (bf16)
__device__ __align__(16) float g_als1[NN * HEADS];
__device__ __align__(16) float g_ald1[NN * HEADS];
__device__ float g_als2[NN], g_ald2[NN];
__device__ __align__(16) float g_pool[NG * HID];

// index handling + CSR (dst-sorted)
__device__ int g_is64;
__device__ int g_src[NE];
__device__ int g_dst[NE];
__device__ int g_bat[NN];
__device__ int g_deg[NN];
__device__ int g_row[NN + 1];
__device__ int g_cur[NN];
__device__ int g_csr_src[NE];

// ---------------- helpers ----------------
__device__ __forceinline__ float leaky(float v) { return v > 0.f ? v : NEG * v; }

__device__ __forceinline__ void red4(float* p, float4 v) {
    asm volatile("red.global.add.v4.f32 [%0], {%1,%2,%3,%4};"
                 :: "l"(p), "f"(v.x), "f"(v.y), "f"(v.z), "f"(v.w) : "memory");
}

__device__ __forceinline__ void unp8(uint4 u, float* f) {
    float2 p;
    p = __bfloat1622float2(*(const __nv_bfloat162*)&u.x); f[0] = p.x; f[1] = p.y;
    p = __bfloat1622float2(*(const __nv_bfloat162*)&u.y); f[2] = p.x; f[3] = p.y;
    p = __bfloat1622float2(*(const __nv_bfloat162*)&u.z); f[4] = p.x; f[5] = p.y;
    p = __bfloat1622float2(*(const __nv_bfloat162*)&u.w); f[6] = p.x; f[7] = p.y;
}

__device__ __forceinline__ unsigned f2tf(float f) {
    unsigned u;
    asm("cvt.rna.tf32.f32 %0, %1;" : "=r"(u) : "f"(f));
    return u;
}

// ---------------- prep: detect index dtype + zero degree array ----------
__global__ void prep_k(const int* __restrict__ raw) {
    int n = blockIdx.x * blockDim.x + threadIdx.x;
    if (n < NN) g_deg[n] = 0;
    if (n == 0) {
        int acc = 0;
#pragma unroll 1
        for (int i = 1; i < 128; i += 2) acc |= raw[i];
        g_is64 = (acc == 0) ? 1 : 0;   // int64 LE: high words all zero
    }
}

__global__ void cvt_k(const int* __restrict__ eraw, const int* __restrict__ braw) {
    int e = blockIdx.x * blockDim.x + threadIdx.x;
    if (e >= NE) return;
    int s, d;
    if (g_is64) {
        const long long* p = (const long long*)eraw;
        s = (int)p[e];
        d = (int)p[(size_t)NE + e];
        if (e < NN) g_bat[e] = (int)((const long long*)braw)[e];
    } else {
        s = eraw[e];
        d = eraw[NE + e];
        if (e < NN) g_bat[e] = braw[e];
    }
    g_src[e] = s;
    g_dst[e] = d;
    atomicAdd(&g_deg[d], 1);
}

// single-block exclusive scan over g_deg -> g_row; inits g_cur
__global__ __launch_bounds__(1024) void scan_k() {
    __shared__ int wsum[32];
    __shared__ int s_carry;
    const int tid = threadIdx.x, lane = tid & 31, wid = tid >> 5;
    if (tid == 0) s_carry = 0;
    __syncthreads();
    for (int base = 0; base < NN; base += 1024) {
        int i = base + tid;
        int v = (i < NN) ? g_deg[i] : 0;
        int incl = v;
#pragma unroll
        for (int off = 1; off < 32; off <<= 1) {
            int t = __shfl_up_sync(0xFFFFFFFFu, incl, off);
            if (lane >= off) incl += t;
        }
        if (lane == 31) wsum[wid] = incl;
        __syncthreads();
        if (wid == 0) {
            int w = wsum[lane];
            int wi = w;
#pragma unroll
            for (int off = 1; off < 32; off <<= 1) {
                int t = __shfl_up_sync(0xFFFFFFFFu, wi, off);
                if (lane >= off) wi += t;
            }
            wsum[lane] = wi - w;
        }
        __syncthreads();
        int c = s_carry;
        int excl = c + wsum[wid] + incl - v;
        if (i < NN) {
            g_row[i] = excl;
            g_cur[i] = excl;
        }
        __syncthreads();
        if (tid == 1023) s_carry = c + wsum[31] + incl;
        __syncthreads();
    }
    if (tid == 0) g_row[NN] = s_carry;
}

__global__ void place_k() {
    int e = blockIdx.x * blockDim.x + threadIdx.x;
    if (e >= NE) return;
    int p = atomicAdd(&g_cur[g_dst[e]], 1);
    g_csr_src[p] = g_src[e];
}

// -------- tf32 tensor-core GEMM: C_bf16[M,N] = A[M,K] @ B[K,N] (fp32 in) ----
// BM=128, BN=64, BK=16; 256 threads = 8 warps (4m x 2n), warp tile 32x32.
// mma.sync.m16n8k8 tf32; cvt.rna at smem store. N%64==0, K%16==0.
__global__ __launch_bounds__(256) void mma_gemm_k(const float* __restrict__ A,
                                                  const float* __restrict__ B,
                                                  __nv_bfloat16* __restrict__ C,
                                                  int M, int N, int K) {
    constexpr int BM = 128, BN = 64, BK = 16;
    __shared__ unsigned As[BM][BK + 4];   // pad 4: frag loads conflict-free
    __shared__ unsigned Bs[BK][BN + 8];   // pad 8: frag loads conflict-free
    const int tid = threadIdx.x;
    const int lane = tid & 31, w = tid >> 5;
    const int wm = (w & 3) * 32, wn = (w >> 2) * 32;
    const int g = lane >> 2, tg = lane & 3;
    const int m0 = blockIdx.y * BM, n0 = blockIdx.x * BN;

    float c[2][4][4];
#pragma unroll
    for (int mt = 0; mt < 2; mt++)
#pragma unroll
        for (int nt = 0; nt < 4; nt++)
#pragma unroll
            for (int r = 0; r < 4; r++) c[mt][nt][r] = 0.f;

    for (int kb = 0; kb < K; kb += BK) {
        {   // A tile 128x16: 2 float4 per thread
            int row = tid >> 2, c4 = (tid & 3) * 4;
#pragma unroll
            for (int r = 0; r < 2; r++) {
                int rr = row + r * 64;
                float4 f = make_float4(0.f, 0.f, 0.f, 0.f);
                if (m0 + rr < M) f = *(const float4*)(A + (size_t)(m0 + rr) * K + kb + c4);
                As[rr][c4 + 0] = f2tf(f.x); As[rr][c4 + 1] = f2tf(f.y);
                As[rr][c4 + 2] = f2tf(f.z); As[rr][c4 + 3] = f2tf(f.w);
            }
        }
        {   // B tile 16x64: 1 float4 per thread
            int row = tid >> 4, c4 = (tid & 15) * 4;
            float4 f = *(const float4*)(B + (size_t)(kb + row) * N + n0 + c4);
            Bs[row][c4 + 0] = f2tf(f.x); Bs[row][c4 + 1] = f2tf(f.y);
            Bs[row][c4 + 2] = f2tf(f.z); Bs[row][c4 + 3] = f2tf(f.w);
        }
        __syncthreads();
#pragma unroll
        for (int kk = 0; kk < 2; kk++) {
            const int k0 = kk * 8;
            unsigned a[2][4], b[4][2];
#pragma unroll
            for (int mt = 0; mt < 2; mt++) {
                int r = wm + mt * 16;
                a[mt][0] = As[r + g][k0 + tg];
                a[mt][1] = As[r + g + 8][k0 + tg];
                a[mt][2] = As[r + g][k0 + tg + 4];
                a[mt][3] = As[r + g + 8][k0 + tg + 4];
            }
#pragma unroll
            for (int nt = 0; nt < 4; nt++) {
                int cc = wn + nt * 8 + g;
                b[nt][0] = Bs[k0 + tg][cc];
                b[nt][1] = Bs[k0 + tg + 4][cc];
            }
#pragma unroll
            for (int mt = 0; mt < 2; mt++)
#pragma unroll
                for (int nt = 0; nt < 4; nt++) {
                    asm volatile(
                        "mma.sync.aligned.m16n8k8.row.col.f32.tf32.tf32.f32 "
                        "{%0,%1,%2,%3}, {%4,%5,%6,%7}, {%8,%9}, {%0,%1,%2,%3};"
                        : "+f"(c[mt][nt][0]), "+f"(c[mt][nt][1]),
                          "+f"(c[mt][nt][2]), "+f"(c[mt][nt][3])
                        : "r"(a[mt][0]), "r"(a[mt][1]), "r"(a[mt][2]), "r"(a[mt][3]),
                          "r"(b[nt][0]), "r"(b[nt][1]));
                }
        }
        __syncthreads();
    }

#pragma unroll
    for (int mt = 0; mt < 2; mt++)
#pragma unroll
        for (int nt = 0; nt < 4; nt++) {
            int row0 = m0 + wm + mt * 16 + g;
            int col = n0 + wn + nt * 8 + tg * 2;
            if (row0 < M)
                *(__nv_bfloat162*)(C + (size_t)row0 * N + col) =
                    __floats2bfloat162_rn(c[mt][nt][0], c[mt][nt][1]);
            if (row0 + 8 < M)
                *(__nv_bfloat162*)(C + (size_t)(row0 + 8) * N + col) =
                    __floats2bfloat162_rn(c[mt][nt][2], c[mt][nt][3]);
        }
}

// ---------------- attention coefficients (bf16 features) ----------------
__global__ void al1_k(const float* __restrict__ a_src, const float* __restrict__ a_dst) {
    int t = blockIdx.x * blockDim.x + threadIdx.x;
    if (t >= NN * HEADS) return;
    int n = t >> 2, h = t & 3;
    const uint4* hr = (const uint4*)(g_h1b + (size_t)n * D1 + h * HID);
    const float4* as = (const float4*)(a_src + h * HID);
    const float4* ad = (const float4*)(a_dst + h * HID);
    float ss = 0.f, sd = 0.f;
#pragma unroll
    for (int j = 0; j < 8; j++) {
        float f[8];
        unp8(hr[j], f);
        float4 a0 = as[2 * j], a1 = as[2 * j + 1];
        float4 b0 = ad[2 * j], b1 = ad[2 * j + 1];
        ss += f[0] * a0.x + f[1] * a0.y + f[2] * a0.z + f[3] * a0.w
            + f[4] * a1.x + f[5] * a1.y + f[6] * a1.z + f[7] * a1.w;
        sd += f[0] * b0.x + f[1] * b0.y + f[2] * b0.z + f[3] * b0.w
            + f[4] * b1.x + f[5] * b1.y + f[6] * b1.z + f[7] * b1.w;
    }
    g_als1[t] = ss;
    g_ald1[t] = sd;
}

// also zeroes the pooled output (independent work, saves a launch)
__global__ void al2_k(const float* __restrict__ a_src, const float* __restrict__ a_dst) {
    int n = blockIdx.x * blockDim.x + threadIdx.x;
    if (n < NG * HID) g_pool[n] = 0.f;
    if (n >= NN) return;
    const uint4* hr = (const uint4*)(g_h2b + (size_t)n * HID);
    const float4* as = (const float4*)a_src;
    const float4* ad = (const float4*)a_dst;
    float ss = 0.f, sd = 0.f;
#pragma unroll
    for (int j = 0; j < 8; j++) {
        float f[8];
        unp8(hr[j], f);
        float4 a0 = as[2 * j], a1 = as[2 * j + 1];
        float4 b0 = ad[2 * j], b1 = ad[2 * j + 1];
        ss += f[0] * a0.x + f[1] * a0.y + f[2] * a0.z + f[3] * a0.w
            + f[4] * a1.x + f[5] * a1.y + f[6] * a1.z + f[7] * a1.w;
        sd += f[0] * b0.x + f[1] * b0.y + f[2] * b0.z + f[3] * b0.w
            + f[4] * b1.x + f[5] * b1.y + f[6] * b1.z + f[7] * b1.w;
    }
    g_als2[n] = ss;
    g_ald2[n] = sd;
}

// ------- layer 1: fused single-pass softmax + aggregate + bias + relu -------
__global__ __launch_bounds__(256) void agg1_k(const float* __restrict__ b1) {
    int node = (blockIdx.x * blockDim.x + threadIdx.x) >> 5;
    int lane = threadIdx.x & 31;
    if (node >= NN) return;
    const int h = lane >> 3;
    const int beg = g_row[node], end = g_row[node + 1];

    const float ald = g_ald1[node * 4 + h];
    float ex = __expf(leaky(g_als1[node * 4 + h] + ald));  // self-loop term
    float den = ex;
    float acc[8];
    {
        float f[8];
        unp8(*(const uint4*)(g_h1b + (size_t)node * D1 + lane * 8), f);
#pragma unroll
        for (int c = 0; c < 8; c++) acc[c] = ex * f[c];
    }
    for (int i = beg; i < end; i++) {
        int s = g_csr_src[i];
        float w = __expf(leaky(g_als1[s * 4 + h] + ald));
        den += w;
        float f[8];
        unp8(*(const uint4*)(g_h1b + (size_t)s * D1 + lane * 8), f);
#pragma unroll
        for (int c = 0; c < 8; c++) acc[c] = fmaf(w, f[c], acc[c]);
    }
    float inv = 1.f / (den + 1e-16f);
    const float4* bp = (const float4*)(b1 + lane * 8);
    float4 b0 = bp[0], b4 = bp[1];
    float4 o0 = make_float4(fmaxf(fmaf(acc[0], inv, b0.x), 0.f),
                            fmaxf(fmaf(acc[1], inv, b0.y), 0.f),
                            fmaxf(fmaf(acc[2], inv, b0.z), 0.f),
                            fmaxf(fmaf(acc[3], inv, b0.w), 0.f));
    float4 o1 = make_float4(fmaxf(fmaf(acc[4], inv, b4.x), 0.f),
                            fmaxf(fmaf(acc[5], inv, b4.y), 0.f),
                            fmaxf(fmaf(acc[6], inv, b4.z), 0.f),
                            fmaxf(fmaf(acc[7], inv, b4.w), 0.f));
    float4* op = (float4*)(g_out1 + (size_t)node * D1 + lane * 8);
    op[0] = o0; op[1] = o1;
}

// ------- layer 2: fused single-pass softmax + aggregate + bias + pool -------
__global__ __launch_bounds__(256) void agg2_k(const float* __restrict__ b2) {
    int node = (blockIdx.x * blockDim.x + threadIdx.x) >> 5;
    int lane = threadIdx.x & 31;
    if (node >= NN) return;
    const int beg = g_row[node], end = g_row[node + 1];

    const float ald = g_ald2[node];
    float ex = __expf(leaky(g_als2[node] + ald));
    float den = ex;
    float a0, a1;
    {
        float2 v = __bfloat1622float2(
            *(const __nv_bfloat162*)(g_h2b + (size_t)node * HID + lane * 2));
        a0 = ex * v.x; a1 = ex * v.y;
    }
    for (int i = beg; i < end; i++) {
        int s = g_csr_src[i];
        float w = __expf(leaky(g_als2[s] + ald));
        den += w;
        float2 v = __bfloat1622float2(
            *(const __nv_bfloat162*)(g_h2b + (size_t)s * HID + lane * 2));
        a0 = fmaf(w, v.x, a0);
        a1 = fmaf(w, v.y, a1);
    }
    float inv = 1.f / (den + 1e-16f);
    float2 bb = *(const float2*)(b2 + lane * 2);
    float v0 = fmaf(a0, inv, bb.x);
    float v1 = fmaf(a1, inv, bb.y);

    float u0 = __shfl_down_sync(0xFFFFFFFFu, v0, 1);
    float u1 = __shfl_down_sync(0xFFFFFFFFu, v1, 1);
    if ((lane & 1) == 0) {
        int g = g_bat[node];
        red4(&g_pool[g * HID + lane * 2], make_float4(v0, v1, u0, u1));
    }
}

// ---------------- classifier ----------------
__global__ void cls_k(const float* __restrict__ fcw, const float* __restrict__ fcb,
                      float* __restrict__ out) {
    int g = blockIdx.x * blockDim.x + threadIdx.x;
    if (g >= NG) return;
    float l[OUTC];
#pragma unroll
    for (int j = 0; j < OUTC; j++) l[j] = fcb[j];
    for (int k = 0; k < HID; k++) {
        float p = g_pool[g * HID + k];
#pragma unroll
        for (int j = 0; j < OUTC; j++) l[j] = fmaf(p, fcw[k * OUTC + j], l[j]);
    }
    float mx = l[0];
#pragma unroll
    for (int j = 1; j < OUTC; j++) mx = fmaxf(mx, l[j]);
    float s = 0.f;
#pragma unroll
    for (int j = 0; j < OUTC; j++) s += expf(l[j] - mx);
    float lse = mx + logf(s);
#pragma unroll
    for (int j = 0; j < OUTC; j++) out[g * OUTC + j] = l[j] - lse;
}

// ---------------- launch ----------------
extern "C" void kernel_launch(void* const* d_in, const int* in_sizes, int n_in,
                              void* d_out, int out_size) {
    const float* x      = (const float*)d_in[0];
    const int*   ei_raw = (const int*)d_in[1];
    const int*   b_raw  = (const int*)d_in[2];
    const float* W1     = (const float*)d_in[3];
    const float* a_src1 = (const float*)d_in[4];
    const float* a_dst1 = (const float*)d_in[5];
    const float* b1     = (const float*)d_in[6];
    const float* W2     = (const float*)d_in[7];
    const float* a_src2 = (const float*)d_in[8];
    const float* a_dst2 = (const float*)d_in[9];
    const float* b2     = (const float*)d_in[10];
    const float* fcw    = (const float*)d_in[11];
    const float* fcb    = (const float*)d_in[12];
    float*       out    = (float*)d_out;

    void *p_h1b, *p_out1, *p_h2b;
    cudaGetSymbolAddress(&p_h1b, g_h1b);
    cudaGetSymbolAddress(&p_out1, g_out1);
    cudaGetSymbolAddress(&p_h2b, g_h2b);

    const int T = 256;
    const int gN4 = (NN * HEADS + T - 1) / T;
    const int gN  = (NN + T - 1) / T;
    const int gE  = (NE + T - 1) / T;
    const int gNw = (NN * 32 + T - 1) / T;   // warp per node
    const int gM  = (NN + 127) / 128;

    // ---- index conversion + CSR build ----
    prep_k<<<gN, T>>>(ei_raw);
    cvt_k<<<gE, T>>>(ei_raw, b_raw);
    scan_k<<<1, 1024>>>();
    place_k<<<gE, T>>>();

    // ---- GAT layer 1 ----
    mma_gemm_k<<<dim3(D1 / 64, gM), 256>>>(x, W1, (__nv_bfloat16*)p_h1b, NN, D1, INC);
    al1_k<<<gN4, T>>>(a_src1, a_dst1);
    agg1_k<<<gNw, T>>>(b1);

    // ---- GAT layer 2 (+ fused pooling) ----
    mma_gemm_k<<<dim3(HID / 64, gM), 256>>>((const float*)p_out1, W2,
                                            (__nv_bfloat16*)p_h2b, NN, HID, D1);
    al2_k<<<gN, T>>>(a_src2, a_dst2);
    agg2_k<<<gNw, T>>>(b2);

    // ---- classifier ----
    cls_k<<<(NG + T - 1) / T, T>>>(fcw, fcb, out);
}

// round 12
// speedup vs baseline: 1.6625x; 1.1311x over previous
#include <cuda_runtime.h>
#include <cuda_bf16.h>
#include <cstdint>
#include <cstddef>

#define NN     50000
#define NE     800000
#define INC    128
#define HID    64
#define HEADS  4
#define D1     256          // HEADS*HID
#define OUTC   10
#define NG     500
#define NEG    0.2f

// ---------------- scratch (device globals; allocation-free) ----------------
__device__ __align__(16) __nv_bfloat16 g_h1b[NN * D1];   // x @ W1   (bf16)
__device__ __align__(16) float         g_out1[NN * D1];  // relu(GAT1 + b1) fp32
__device__ __align__(16) __nv_bfloat16 g_h2b[NN * HID];  // out1 @ W2 (bf16)
__device__ __align__(16) float g_als1[NN * HEADS];
__device__ __align__(16) float g_ald1[NN * HEADS];
__device__ float g_als2[NN], g_ald2[NN];
__device__ __align__(16) float g_pool[NG * HID];

// index handling + CSR (dst-sorted)
__device__ int g_is64;
__device__ int g_src[NE];
__device__ int g_dst[NE];
__device__ int g_bat[NN];
__device__ int g_deg[NN];
__device__ int g_row[NN + 1];
__device__ int g_cur[NN];
__device__ int g_csr_src[NE];

// ---------------- helpers ----------------
__device__ __forceinline__ float leaky(float v) { return v > 0.f ? v : NEG * v; }

__device__ __forceinline__ void red4(float* p, float4 v) {
    asm volatile("red.global.add.v4.f32 [%0], {%1,%2,%3,%4};"
                 :: "l"(p), "f"(v.x), "f"(v.y), "f"(v.z), "f"(v.w) : "memory");
}

__device__ __forceinline__ void unp8(uint4 u, float* f) {
    float2 p;
    p = __bfloat1622float2(*(const __nv_bfloat162*)&u.x); f[0] = p.x; f[1] = p.y;
    p = __bfloat1622float2(*(const __nv_bfloat162*)&u.y); f[2] = p.x; f[3] = p.y;
    p = __bfloat1622float2(*(const __nv_bfloat162*)&u.z); f[4] = p.x; f[5] = p.y;
    p = __bfloat1622float2(*(const __nv_bfloat162*)&u.w); f[6] = p.x; f[7] = p.y;
}

__device__ __forceinline__ unsigned f2tf(float f) {
    unsigned u;
    asm("cvt.rna.tf32.f32 %0, %1;" : "=r"(u) : "f"(f));
    return u;
}

// ---------------- prep: detect index dtype + zero degree array ----------
__global__ void prep_k(const int* __restrict__ raw) {
    int n = blockIdx.x * blockDim.x + threadIdx.x;
    if (n < NN) g_deg[n] = 0;
    if (n == 0) {
        int acc = 0;
#pragma unroll 1
        for (int i = 1; i < 128; i += 2) acc |= raw[i];
        g_is64 = (acc == 0) ? 1 : 0;   // int64 LE: high words all zero
    }
}

__global__ void cvt_k(const int* __restrict__ eraw, const int* __restrict__ braw) {
    int e = blockIdx.x * blockDim.x + threadIdx.x;
    if (e >= NE) return;
    int s, d;
    if (g_is64) {
        const long long* p = (const long long*)eraw;
        s = (int)p[e];
        d = (int)p[(size_t)NE + e];
        if (e < NN) g_bat[e] = (int)((const long long*)braw)[e];
    } else {
        s = eraw[e];
        d = eraw[NE + e];
        if (e < NN) g_bat[e] = braw[e];
    }
    g_src[e] = s;
    g_dst[e] = d;
    atomicAdd(&g_deg[d], 1);
}

// single-block exclusive scan over g_deg -> g_row; inits g_cur
__global__ __launch_bounds__(1024) void scan_k() {
    __shared__ int wsum[32];
    __shared__ int s_carry;
    const int tid = threadIdx.x, lane = tid & 31, wid = tid >> 5;
    if (tid == 0) s_carry = 0;
    __syncthreads();
    for (int base = 0; base < NN; base += 1024) {
        int i = base + tid;
        int v = (i < NN) ? g_deg[i] : 0;
        int incl = v;
#pragma unroll
        for (int off = 1; off < 32; off <<= 1) {
            int t = __shfl_up_sync(0xFFFFFFFFu, incl, off);
            if (lane >= off) incl += t;
        }
        if (lane == 31) wsum[wid] = incl;
        __syncthreads();
        if (wid == 0) {
            int w = wsum[lane];
            int wi = w;
#pragma unroll
            for (int off = 1; off < 32; off <<= 1) {
                int t = __shfl_up_sync(0xFFFFFFFFu, wi, off);
                if (lane >= off) wi += t;
            }
            wsum[lane] = wi - w;
        }
        __syncthreads();
        int c = s_carry;
        int excl = c + wsum[wid] + incl - v;
        if (i < NN) {
            g_row[i] = excl;
            g_cur[i] = excl;
        }
        __syncthreads();
        if (tid == 1023) s_carry = c + wsum[31] + incl;
        __syncthreads();
    }
    if (tid == 0) g_row[NN] = s_carry;
}

__global__ void place_k() {
    int e = blockIdx.x * blockDim.x + threadIdx.x;
    if (e >= NE) return;
    int p = atomicAdd(&g_cur[g_dst[e]], 1);
    g_csr_src[p] = g_src[e];
}

// -------- tf32 tensor-core GEMM: C_bf16[M,N] = A[M,K] @ B[K,N] (fp32 in) ----
// BM=128, BN=64, BK=16; 256 threads = 8 warps (4m x 2n), warp tile 32x32.
__global__ __launch_bounds__(256) void mma_gemm_k(const float* __restrict__ A,
                                                  const float* __restrict__ B,
                                                  __nv_bfloat16* __restrict__ C,
                                                  int M, int N, int K) {
    constexpr int BM = 128, BN = 64, BK = 16;
    __shared__ unsigned As[BM][BK + 4];
    __shared__ unsigned Bs[BK][BN + 8];
    const int tid = threadIdx.x;
    const int lane = tid & 31, w = tid >> 5;
    const int wm = (w & 3) * 32, wn = (w >> 2) * 32;
    const int g = lane >> 2, tg = lane & 3;
    const int m0 = blockIdx.y * BM, n0 = blockIdx.x * BN;

    float c[2][4][4];
#pragma unroll
    for (int mt = 0; mt < 2; mt++)
#pragma unroll
        for (int nt = 0; nt < 4; nt++)
#pragma unroll
            for (int r = 0; r < 4; r++) c[mt][nt][r] = 0.f;

    for (int kb = 0; kb < K; kb += BK) {
        {   // A tile 128x16: 2 float4 per thread
            int row = tid >> 2, c4 = (tid & 3) * 4;
#pragma unroll
            for (int r = 0; r < 2; r++) {
                int rr = row + r * 64;
                float4 f = make_float4(0.f, 0.f, 0.f, 0.f);
                if (m0 + rr < M) f = *(const float4*)(A + (size_t)(m0 + rr) * K + kb + c4);
                As[rr][c4 + 0] = f2tf(f.x); As[rr][c4 + 1] = f2tf(f.y);
                As[rr][c4 + 2] = f2tf(f.z); As[rr][c4 + 3] = f2tf(f.w);
            }
        }
        {   // B tile 16x64: 1 float4 per thread
            int row = tid >> 4, c4 = (tid & 15) * 4;
            float4 f = *(const float4*)(B + (size_t)(kb + row) * N + n0 + c4);
            Bs[row][c4 + 0] = f2tf(f.x); Bs[row][c4 + 1] = f2tf(f.y);
            Bs[row][c4 + 2] = f2tf(f.z); Bs[row][c4 + 3] = f2tf(f.w);
        }
        __syncthreads();
#pragma unroll
        for (int kk = 0; kk < 2; kk++) {
            const int k0 = kk * 8;
            unsigned a[2][4], b[4][2];
#pragma unroll
            for (int mt = 0; mt < 2; mt++) {
                int r = wm + mt * 16;
                a[mt][0] = As[r + g][k0 + tg];
                a[mt][1] = As[r + g + 8][k0 + tg];
                a[mt][2] = As[r + g][k0 + tg + 4];
                a[mt][3] = As[r + g + 8][k0 + tg + 4];
            }
#pragma unroll
            for (int nt = 0; nt < 4; nt++) {
                int cc = wn + nt * 8 + g;
                b[nt][0] = Bs[k0 + tg][cc];
                b[nt][1] = Bs[k0 + tg + 4][cc];
            }
#pragma unroll
            for (int mt = 0; mt < 2; mt++)
#pragma unroll
                for (int nt = 0; nt < 4; nt++) {
                    asm volatile(
                        "mma.sync.aligned.m16n8k8.row.col.f32.tf32.tf32.f32 "
                        "{%0,%1,%2,%3}, {%4,%5,%6,%7}, {%8,%9}, {%0,%1,%2,%3};"
                        : "+f"(c[mt][nt][0]), "+f"(c[mt][nt][1]),
                          "+f"(c[mt][nt][2]), "+f"(c[mt][nt][3])
                        : "r"(a[mt][0]), "r"(a[mt][1]), "r"(a[mt][2]), "r"(a[mt][3]),
                          "r"(b[nt][0]), "r"(b[nt][1]));
                }
        }
        __syncthreads();
    }

#pragma unroll
    for (int mt = 0; mt < 2; mt++)
#pragma unroll
        for (int nt = 0; nt < 4; nt++) {
            int row0 = m0 + wm + mt * 16 + g;
            int col = n0 + wn + nt * 8 + tg * 2;
            if (row0 < M)
                *(__nv_bfloat162*)(C + (size_t)row0 * N + col) =
                    __floats2bfloat162_rn(c[mt][nt][0], c[mt][nt][1]);
            if (row0 + 8 < M)
                *(__nv_bfloat162*)(C + (size_t)(row0 + 8) * N + col) =
                    __floats2bfloat162_rn(c[mt][nt][2], c[mt][nt][3]);
        }
}

// ---------------- attention coefficients (bf16 features) ----------------
__global__ void al1_k(const float* __restrict__ a_src, const float* __restrict__ a_dst) {
    int t = blockIdx.x * blockDim.x + threadIdx.x;
    if (t >= NN * HEADS) return;
    int n = t >> 2, h = t & 3;
    const uint4* hr = (const uint4*)(g_h1b + (size_t)n * D1 + h * HID);
    const float4* as = (const float4*)(a_src + h * HID);
    const float4* ad = (const float4*)(a_dst + h * HID);
    float ss = 0.f, sd = 0.f;
#pragma unroll
    for (int j = 0; j < 8; j++) {
        float f[8];
        unp8(hr[j], f);
        float4 a0 = as[2 * j], a1 = as[2 * j + 1];
        float4 b0 = ad[2 * j], b1 = ad[2 * j + 1];
        ss += f[0] * a0.x + f[1] * a0.y + f[2] * a0.z + f[3] * a0.w
            + f[4] * a1.x + f[5] * a1.y + f[6] * a1.z + f[7] * a1.w;
        sd += f[0] * b0.x + f[1] * b0.y + f[2] * b0.z + f[3] * b0.w
            + f[4] * b1.x + f[5] * b1.y + f[6] * b1.z + f[7] * b1.w;
    }
    g_als1[t] = ss;
    g_ald1[t] = sd;
}

// also zeroes the pooled output (independent work, saves a launch)
__global__ void al2_k(const float* __restrict__ a_src, const float* __restrict__ a_dst) {
    int n = blockIdx.x * blockDim.x + threadIdx.x;
    if (n < NG * HID) g_pool[n] = 0.f;
    if (n >= NN) return;
    const uint4* hr = (const uint4*)(g_h2b + (size_t)n * HID);
    const float4* as = (const float4*)a_src;
    const float4* ad = (const float4*)a_dst;
    float ss = 0.f, sd = 0.f;
#pragma unroll
    for (int j = 0; j < 8; j++) {
        float f[8];
        unp8(hr[j], f);
        float4 a0 = as[2 * j], a1 = as[2 * j + 1];
        float4 b0 = ad[2 * j], b1 = ad[2 * j + 1];
        ss += f[0] * a0.x + f[1] * a0.y + f[2] * a0.z + f[3] * a0.w
            + f[4] * a1.x + f[5] * a1.y + f[6] * a1.z + f[7] * a1.w;
        sd += f[0] * b0.x + f[1] * b0.y + f[2] * b0.z + f[3] * b0.w
            + f[4] * b1.x + f[5] * b1.y + f[6] * b1.z + f[7] * b1.w;
    }
    g_als2[n] = ss;
    g_ald2[n] = sd;
}

// ------- layer 1: fused single-pass softmax + aggregate + bias + relu -------
__global__ __launch_bounds__(256) void agg1_k(const float* __restrict__ b1) {
    int node = (blockIdx.x * blockDim.x + threadIdx.x) >> 5;
    int lane = threadIdx.x & 31;
    if (node >= NN) return;
    const int h = lane >> 3;
    const int beg = g_row[node], end = g_row[node + 1];

    const float ald = g_ald1[node * 4 + h];
    float ex = __expf(leaky(g_als1[node * 4 + h] + ald));  // self-loop term
    float den = ex;
    float acc[8];
    {
        float f[8];
        unp8(*(const uint4*)(g_h1b + (size_t)node * D1 + lane * 8), f);
#pragma unroll
        for (int c = 0; c < 8; c++) acc[c] = ex * f[c];
    }
    for (int i = beg; i < end; i++) {
        int s = g_csr_src[i];
        float w = __expf(leaky(g_als1[s * 4 + h] + ald));
        den += w;
        float f[8];
        unp8(*(const uint4*)(g_h1b + (size_t)s * D1 + lane * 8), f);
#pragma unroll
        for (int c = 0; c < 8; c++) acc[c] = fmaf(w, f[c], acc[c]);
    }
    float inv = 1.f / (den + 1e-16f);
    const float4* bp = (const float4*)(b1 + lane * 8);
    float4 b0 = bp[0], b4 = bp[1];
    float4 o0 = make_float4(fmaxf(fmaf(acc[0], inv, b0.x), 0.f),
                            fmaxf(fmaf(acc[1], inv, b0.y), 0.f),
                            fmaxf(fmaf(acc[2], inv, b0.z), 0.f),
                            fmaxf(fmaf(acc[3], inv, b0.w), 0.f));
    float4 o1 = make_float4(fmaxf(fmaf(acc[4], inv, b4.x), 0.f),
                            fmaxf(fmaf(acc[5], inv, b4.y), 0.f),
                            fmaxf(fmaf(acc[6], inv, b4.z), 0.f),
                            fmaxf(fmaf(acc[7], inv, b4.w), 0.f));
    float4* op = (float4*)(g_out1 + (size_t)node * D1 + lane * 8);
    op[0] = o0; op[1] = o1;
}

// ------- layer 2: fused single-pass softmax + aggregate + bias + pool -------
__global__ __launch_bounds__(256) void agg2_k(const float* __restrict__ b2) {
    int node = (blockIdx.x * blockDim.x + threadIdx.x) >> 5;
    int lane = threadIdx.x & 31;
    if (node >= NN) return;
    const int beg = g_row[node], end = g_row[node + 1];

    const float ald = g_ald2[node];
    float ex = __expf(leaky(g_als2[node] + ald));
    float den = ex;
    float a0, a1;
    {
        float2 v = __bfloat1622float2(
            *(const __nv_bfloat162*)(g_h2b + (size_t)node * HID + lane * 2));
        a0 = ex * v.x; a1 = ex * v.y;
    }
    for (int i = beg; i < end; i++) {
        int s = g_csr_src[i];
        float w = __expf(leaky(g_als2[s] + ald));
        den += w;
        float2 v = __bfloat1622float2(
            *(const __nv_bfloat162*)(g_h2b + (size_t)s * HID + lane * 2));
        a0 = fmaf(w, v.x, a0);
        a1 = fmaf(w, v.y, a1);
    }
    float inv = 1.f / (den + 1e-16f);
    float2 bb = *(const float2*)(b2 + lane * 2);
    float v0 = fmaf(a0, inv, bb.x);
    float v1 = fmaf(a1, inv, bb.y);

    float u0 = __shfl_down_sync(0xFFFFFFFFu, v0, 1);
    float u1 = __shfl_down_sync(0xFFFFFFFFu, v1, 1);
    if ((lane & 1) == 0) {
        int g = g_bat[node];
        red4(&g_pool[g * HID + lane * 2], make_float4(v0, v1, u0, u1));
    }
}

// ---------------- classifier ----------------
__global__ void cls_k(const float* __restrict__ fcw, const float* __restrict__ fcb,
                      float* __restrict__ out) {
    int g = blockIdx.x * blockDim.x + threadIdx.x;
    if (g >= NG) return;
    float l[OUTC];
#pragma unroll
    for (int j = 0; j < OUTC; j++) l[j] = fcb[j];
    for (int k = 0; k < HID; k++) {
        float p = g_pool[g * HID + k];
#pragma unroll
        for (int j = 0; j < OUTC; j++) l[j] = fmaf(p, fcw[k * OUTC + j], l[j]);
    }
    float mx = l[0];
#pragma unroll
    for (int j = 1; j < OUTC; j++) mx = fmaxf(mx, l[j]);
    float s = 0.f;
#pragma unroll
    for (int j = 0; j < OUTC; j++) s += expf(l[j] - mx);
    float lse = mx + logf(s);
#pragma unroll
    for (int j = 0; j < OUTC; j++) out[g * OUTC + j] = l[j] - lse;
}

// ---------------- launch ----------------
extern "C" void kernel_launch(void* const* d_in, const int* in_sizes, int n_in,
                              void* d_out, int out_size) {
    const float* x      = (const float*)d_in[0];
    const int*   ei_raw = (const int*)d_in[1];
    const int*   b_raw  = (const int*)d_in[2];
    const float* W1     = (const float*)d_in[3];
    const float* a_src1 = (const float*)d_in[4];
    const float* a_dst1 = (const float*)d_in[5];
    const float* b1     = (const float*)d_in[6];
    const float* W2     = (const float*)d_in[7];
    const float* a_src2 = (const float*)d_in[8];
    const float* a_dst2 = (const float*)d_in[9];
    const float* b2     = (const float*)d_in[10];
    const float* fcw    = (const float*)d_in[11];
    const float* fcb    = (const float*)d_in[12];
    float*       out    = (float*)d_out;

    void *p_h1b, *p_out1, *p_h2b;
    cudaGetSymbolAddress(&p_h1b, g_h1b);
    cudaGetSymbolAddress(&p_out1, g_out1);
    cudaGetSymbolAddress(&p_h2b, g_h2b);

    // one-time stream/event creation (first call is the uncaptured correctness
    // run; subsequent captured calls reuse them — no allocs during capture)
    static cudaStream_t s_aux = nullptr;
    static cudaEvent_t ev_fork = nullptr, ev_join = nullptr;
    if (s_aux == nullptr) {
        cudaStreamCreateWithFlags(&s_aux, cudaStreamNonBlocking);
        cudaEventCreateWithFlags(&ev_fork, cudaEventDisableTiming);
        cudaEventCreateWithFlags(&ev_join, cudaEventDisableTiming);
    }

    const int T = 256;
    const int gN4 = (NN * HEADS + T - 1) / T;
    const int gN  = (NN + T - 1) / T;
    const int gE  = (NE + T - 1) / T;
    const int gNw = (NN * 32 + T - 1) / T;   // warp per node
    const int gM  = (NN + 127) / 128;

    // ---- fork: CSR build chain on s_aux, concurrent with GEMM1 chain ----
    cudaEventRecord(ev_fork, 0);
    cudaStreamWaitEvent(s_aux, ev_fork, 0);
    prep_k<<<gN, T, 0, s_aux>>>(ei_raw);
    cvt_k<<<gE, T, 0, s_aux>>>(ei_raw, b_raw);
    scan_k<<<1, 1024, 0, s_aux>>>();
    place_k<<<gE, T, 0, s_aux>>>();
    cudaEventRecord(ev_join, s_aux);

    // ---- GAT layer 1 feature chain (independent of CSR) ----
    mma_gemm_k<<<dim3(D1 / 64, gM), 256>>>(x, W1, (__nv_bfloat16*)p_h1b, NN, D1, INC);
    al1_k<<<gN4, T>>>(a_src1, a_dst1);

    // ---- join: aggregation needs both chains ----
    cudaStreamWaitEvent(0, ev_join, 0);
    agg1_k<<<gNw, T>>>(b1);

    // ---- GAT layer 2 (+ fused pooling) ----
    mma_gemm_k<<<dim3(HID / 64, gM), 256>>>((const float*)p_out1, W2,
                                            (__nv_bfloat16*)p_h2b, NN, HID, D1);
    al2_k<<<gN, T>>>(a_src2, a_dst2);
    agg2_k<<<gNw, T>>>(b2);

    // ---- classifier ----
    cls_k<<<(NG + T - 1) / T, T>>>(fcw, fcb, out);
}